// round 11
// baseline (speedup 1.0000x reference)
#include <cuda_runtime.h>
#include <cuda_bf16.h>
#include <climits>

// ---------------------------------------------------------------------------
// Problem constants
// ---------------------------------------------------------------------------
constexpr int BATCH  = 128;
constexpr int NPTS   = 65536;
constexpr int NPT    = 10;     // NPOINT
constexpr int NS     = 8;      // NSAMPLE
constexpr int NPOS   = BATCH * NPT * NS;  // 10240 positions

constexpr int FPS_T  = 1024;
constexpr int VPT    = NPTS / (4 * FPS_T);   // 16 float4 dist slots per thread
constexpr int VSM    = 13;                   // dist slots in shared memory
constexpr int VRG    = VPT - VSM;            // dist slots in registers (3)
constexpr int CAP    = 256;                  // per-centroid hit buffer capacity
constexpr int DSMEM  = VSM * FPS_T * 16;     // 208 KB dynamic shared

// ---------------------------------------------------------------------------
// Device scratch (no allocations allowed)
// ---------------------------------------------------------------------------
__device__ float g_grouped[NPOS * 3];         // relative coords [b][s][k][c]
__device__ float g_act1[NPOS * 8];
__device__ float g_act2[NPOS * 8];
__device__ float g_feat[BATCH * 160];
__device__ float g_h[BATCH * 128];

// ---------------------------------------------------------------------------
// Helper: deterministic block reduction of (sum, sumsq) in double
// ---------------------------------------------------------------------------
template <int NWARP>
__device__ __forceinline__ void block_red2(double& s, double& s2, double* sm) {
    const unsigned full = 0xFFFFFFFFu;
    #pragma unroll
    for (int off = 16; off > 0; off >>= 1) {
        s  += __shfl_down_sync(full, s,  off);
        s2 += __shfl_down_sync(full, s2, off);
    }
    int w = threadIdx.x >> 5, l = threadIdx.x & 31;
    if (l == 0) { sm[w * 2] = s; sm[w * 2 + 1] = s2; }
    __syncthreads();
    if (threadIdx.x == 0) {
        double a = 0.0, b = 0.0;
        #pragma unroll
        for (int i = 0; i < NWARP; i++) { a += sm[i * 2]; b += sm[i * 2 + 1]; }
        sm[0] = a; sm[1] = b;
    }
    __syncthreads();
    s = sm[0]; s2 = sm[1];
}

// exact unfused squared distance (matches reference bit-for-bit)
__device__ __forceinline__ float sqd(float x, float y, float z,
                                     float cx, float cy, float cz) {
    float dx = __fadd_rn(x, -cx);
    float dy = __fadd_rn(y, -cy);
    float dz = __fadd_rn(z, -cz);
    return __fadd_rn(__fadd_rn(__fmul_rn(dx, dx), __fmul_rn(dy, dy)),
                     __fmul_rn(dz, dz));
}

// update one float4 dist slot against centroid, track argmax (first-max kept)
__device__ __forceinline__ void upd4(float4& D, float4 X, float4 Y, float4 Z,
                                     float cx, float cy, float cz,
                                     int nb, float& bv, int& bi) {
    float d0 = fminf(D.x, sqd(X.x, Y.x, Z.x, cx, cy, cz));
    float d1 = fminf(D.y, sqd(X.y, Y.y, Z.y, cx, cy, cz));
    float d2 = fminf(D.z, sqd(X.z, Y.z, Z.z, cx, cy, cz));
    float d3 = fminf(D.w, sqd(X.w, Y.w, Z.w, cx, cy, cz));
    D = make_float4(d0, d1, d2, d3);
    if (d0 > bv) { bv = d0; bi = nb; }
    if (d1 > bv) { bv = d1; bi = nb + 1; }
    if (d2 > bv) { bv = d2; bi = nb + 2; }
    if (d3 > bv) { bv = d3; bi = nb + 3; }
}

// ---------------------------------------------------------------------------
// Fused FPS + ball-query + grouping. grid=128, one batch per CTA.
// dist lives in 208 KB dynamic smem (13 float4/thread) + registers
// (3 float4/thread) -> ZERO dist traffic to L1/L2/DRAM. Coords working set
// (96 MB) is L2-resident across the 9 sweeps. Scan order ascending in n per
// thread preserves reference first-max argmax semantics.
// ---------------------------------------------------------------------------
extern __shared__ float4 s_dist4[];   // [VSM][FPS_T]

__global__ void __launch_bounds__(FPS_T, 1) fps_bq_kernel(const float* __restrict__ pc) {
    const int b = blockIdx.x;
    const int t = threadIdx.x;
    const int lane = t & 31, wid = t >> 5;
    const float* __restrict__ px = pc + (size_t)b * 3 * NPTS;
    const float4* __restrict__ px4 = (const float4*)px;
    const float4* __restrict__ py4 = (const float4*)(px + NPTS);
    const float4* __restrict__ pz4 = (const float4*)(px + 2 * NPTS);
    const float* __restrict__ pxs = px;
    const float* __restrict__ pys = px + NPTS;
    const float* __restrict__ pzs = px + 2 * NPTS;

    __shared__ float s_cent[NPT * 3];
    __shared__ float s_cn2[NPT];
    __shared__ float s_wval[32];
    __shared__ int   s_widx[32];
    __shared__ int   s_cnt[NPT];
    __shared__ int   s_hits[NPT][CAP];   // 10 KB

    const float4 INITD = make_float4(1e10f, 1e10f, 1e10f, 1e10f);
    #pragma unroll
    for (int i = 0; i < VSM; i++) s_dist4[i * FPS_T + t] = INITD;
    float4 dreg[VRG];
    #pragma unroll
    for (int i = 0; i < VRG; i++) dreg[i] = INITD;

    if (t == 0) {
        s_cent[0] = pxs[0]; s_cent[1] = pys[0]; s_cent[2] = pzs[0];
    }
    __syncthreads();

    // ------------------------- FPS (9 argmax passes) -------------------------
    for (int it = 1; it < NPT; ++it) {
        const float cx = s_cent[(it - 1) * 3];
        const float cy = s_cent[(it - 1) * 3 + 1];
        const float cz = s_cent[(it - 1) * 3 + 2];
        float bv = -1e30f;
        int   bi = 0;
        #pragma unroll
        for (int i = 0; i < VSM; i++) {            // slots 0..12 (smem)
            int v = t + i * FPS_T;
            float4 D = s_dist4[i * FPS_T + t];
            upd4(D, px4[v], py4[v], pz4[v], cx, cy, cz, 4 * v, bv, bi);
            s_dist4[i * FPS_T + t] = D;
        }
        #pragma unroll
        for (int i = 0; i < VRG; i++) {            // slots 13..15 (registers)
            int v = t + (VSM + i) * FPS_T;
            upd4(dreg[i], px4[v], py4[v], pz4[v], cx, cy, cz, 4 * v, bv, bi);
        }
        // warp argmax (min-index tie-break)
        #pragma unroll
        for (int off = 16; off > 0; off >>= 1) {
            float ov = __shfl_down_sync(0xFFFFFFFFu, bv, off);
            int   oi = __shfl_down_sync(0xFFFFFFFFu, bi, off);
            if (ov > bv || (ov == bv && oi < bi)) { bv = ov; bi = oi; }
        }
        if (lane == 0) { s_wval[wid] = bv; s_widx[wid] = bi; }
        __syncthreads();
        if (t < 32) {
            bv = s_wval[t]; bi = s_widx[t];
            #pragma unroll
            for (int off = 16; off > 0; off >>= 1) {
                float ov = __shfl_down_sync(0xFFFFFFFFu, bv, off);
                int   oi = __shfl_down_sync(0xFFFFFFFFu, bi, off);
                if (ov > bv || (ov == bv && oi < bi)) { bv = ov; bi = oi; }
            }
            if (t == 0) {
                s_cent[it * 3]     = pxs[bi];
                s_cent[it * 3 + 1] = pys[bi];
                s_cent[it * 3 + 2] = pzs[bi];
            }
        }
        __syncthreads();
    }

    // ------------------------- ball query pass -------------------------
    if (t < NPT) {
        float cx = s_cent[t * 3], cy = s_cent[t * 3 + 1], cz = s_cent[t * 3 + 2];
        s_cn2[t] = __fadd_rn(__fadd_rn(__fmul_rn(cx, cx), __fmul_rn(cy, cy)),
                             __fmul_rn(cz, cz));
        s_cnt[t] = 0;
    }
    __syncthreads();

    const float R2 = 0.04f;
    for (int i = 0; i < VPT; i++) {
        int v = t + i * FPS_T;
        int nb = 4 * v;
        float4 X = px4[v], Y = py4[v], Z = pz4[v];
        float xs[4] = {X.x, X.y, X.z, X.w};
        float ys[4] = {Y.x, Y.y, Y.z, Y.w};
        float zs[4] = {Z.x, Z.y, Z.z, Z.w};
        #pragma unroll
        for (int j = 0; j < 4; j++) {
            float x = xs[j], y = ys[j], z = zs[j];
            float pn2 = __fadd_rn(__fadd_rn(__fmul_rn(x, x), __fmul_rn(y, y)),
                                  __fmul_rn(z, z));
            #pragma unroll
            for (int c = 0; c < NPT; c++) {
                float cx = s_cent[c * 3], cy = s_cent[c * 3 + 1], cz = s_cent[c * 3 + 2];
                float dot = __fadd_rn(__fadd_rn(__fmul_rn(cx, x), __fmul_rn(cy, y)),
                                      __fmul_rn(cz, z));
                float sq  = __fadd_rn(__fadd_rn(s_cn2[c], pn2), -__fmul_rn(2.0f, dot));
                if (sq <= R2) {
                    int p = atomicAdd(&s_cnt[c], 1);
                    if (p < CAP) s_hits[c][p] = nb + j;
                }
            }
        }
    }
    __syncthreads();

    // -------- select 8 smallest indices per centroid (one warp each) --------
    if (wid < NPT) {
        const int c = wid;
        int cnt = s_cnt[c]; if (cnt > CAP) cnt = CAP;
        int mysel = INT_MAX;   // index chosen at selection step k == lane
        int first = INT_MAX;
        for (int k = 0; k < NS; k++) {
            int mymin = INT_MAX, mypos = -1;
            for (int j = lane; j < cnt; j += 32) {
                int vv = s_hits[c][j];
                if (vv < mymin) { mymin = vv; mypos = j; }
            }
            #pragma unroll
            for (int off = 16; off > 0; off >>= 1) {
                int ov = __shfl_down_sync(0xFFFFFFFFu, mymin, off);
                int op = __shfl_down_sync(0xFFFFFFFFu, mypos, off);
                if (ov < mymin) { mymin = ov; mypos = op; }
            }
            mymin = __shfl_sync(0xFFFFFFFFu, mymin, 0);
            mypos = __shfl_sync(0xFFFFFFFFu, mypos, 0);
            if (k == 0) first = mymin;
            if (lane == k) mysel = mymin;
            if (lane == 0 && mymin != INT_MAX) s_hits[c][mypos] = INT_MAX;
            __syncwarp();
        }
        if (lane < NS) {
            int n = (mysel == INT_MAX) ? first : mysel;   // pad with first hit
            const float cx = s_cent[c * 3], cy = s_cent[c * 3 + 1], cz = s_cent[c * 3 + 2];
            float* o = &g_grouped[((b * NPT + c) * NS + lane) * 3];
            o[0] = __fadd_rn(pxs[n], -cx);
            o[1] = __fadd_rn(pys[n], -cy);
            o[2] = __fadd_rn(pzs[n], -cz);
        }
    }
}

// ---------------------------------------------------------------------------
// Tail (unchanged, verified): one CTA per channel/feature.
// ---------------------------------------------------------------------------
__global__ void __launch_bounds__(1024) layer1_kernel(
    const float* __restrict__ w, const float* __restrict__ bias,
    const float* __restrict__ g, const float* __restrict__ be) {
    const int c = blockIdx.x, t = threadIdx.x;
    const float w0 = w[c * 3], w1 = w[c * 3 + 1], w2 = w[c * 3 + 2], bb = bias[c];
    float z[10];
    float sf = 0.0f, s2f = 0.0f;
    #pragma unroll
    for (int i = 0; i < 10; i++) {
        int pos = t + i * 1024;
        const float* x = &g_grouped[pos * 3];
        float zz = w0 * x[0] + w1 * x[1] + w2 * x[2] + bb;
        z[i] = zz; sf += zz; s2f += zz * zz;
    }
    double s = sf, s2 = s2f;
    __shared__ double red[64];
    block_red2<32>(s, s2, red);
    __shared__ float s_sc, s_sh;
    if (t == 0) {
        double mean = s / NPOS;
        double var  = s2 / NPOS - mean * mean;
        float inv = rsqrtf((float)var + 1e-5f) * g[c];
        s_sc = inv; s_sh = be[c] - (float)mean * inv;
    }
    __syncthreads();
    const float sc = s_sc, sh = s_sh;
    #pragma unroll
    for (int i = 0; i < 10; i++) {
        int pos = t + i * 1024;
        g_act1[pos * 8 + c] = fmaxf(z[i] * sc + sh, 0.0f);
    }
}

__global__ void __launch_bounds__(1024) layer2_kernel(
    const float* __restrict__ w, const float* __restrict__ bias,
    const float* __restrict__ g, const float* __restrict__ be) {
    const int c = blockIdx.x, t = threadIdx.x;
    float wr[8];
    #pragma unroll
    for (int j = 0; j < 8; j++) wr[j] = w[c * 8 + j];
    const float bb = bias[c];
    float z[10];
    float sf = 0.0f, s2f = 0.0f;
    #pragma unroll
    for (int i = 0; i < 10; i++) {
        int pos = t + i * 1024;
        const float* a = &g_act1[pos * 8];
        float zz = bb;
        #pragma unroll
        for (int j = 0; j < 8; j++) zz += wr[j] * a[j];
        z[i] = zz; sf += zz; s2f += zz * zz;
    }
    double s = sf, s2 = s2f;
    __shared__ double red[64];
    block_red2<32>(s, s2, red);
    __shared__ float s_sc, s_sh;
    if (t == 0) {
        double mean = s / NPOS;
        double var  = s2 / NPOS - mean * mean;
        float inv = rsqrtf((float)var + 1e-5f) * g[c];
        s_sc = inv; s_sh = be[c] - (float)mean * inv;
    }
    __syncthreads();
    const float sc = s_sc, sh = s_sh;
    #pragma unroll
    for (int i = 0; i < 10; i++) {
        int pos = t + i * 1024;
        g_act2[pos * 8 + c] = fmaxf(z[i] * sc + sh, 0.0f);
    }
}

__global__ void __launch_bounds__(1024) layer3_kernel(
    const float* __restrict__ w, const float* __restrict__ bias,
    const float* __restrict__ g, const float* __restrict__ be) {
    const int c = blockIdx.x, t = threadIdx.x;
    float wr[8];
    #pragma unroll
    for (int j = 0; j < 8; j++) wr[j] = w[c * 8 + j];
    const float bb = bias[c];
    float z[10];
    float sf = 0.0f, s2f = 0.0f;
    #pragma unroll
    for (int i = 0; i < 10; i++) {
        int pos = t + i * 1024;
        const float* a = &g_act2[pos * 8];
        float zz = bb;
        #pragma unroll
        for (int j = 0; j < 8; j++) zz += wr[j] * a[j];
        z[i] = zz; sf += zz; s2f += zz * zz;
    }
    double s = sf, s2 = s2f;
    __shared__ double red[64];
    block_red2<32>(s, s2, red);
    __shared__ float s_sc, s_sh;
    if (t == 0) {
        double mean = s / NPOS;
        double var  = s2 / NPOS - mean * mean;
        float inv = rsqrtf((float)var + 1e-5f) * g[c];
        s_sc = inv; s_sh = be[c] - (float)mean * inv;
    }
    __syncthreads();
    const float sc = s_sc, sh = s_sh;
    __shared__ float sa[NPOS];  // 40 KB
    #pragma unroll
    for (int i = 0; i < 10; i++) {
        int pos = t + i * 1024;
        sa[pos] = fmaxf(z[i] * sc + sh, 0.0f);
    }
    __syncthreads();
    for (int gidx = t; gidx < BATCH * NPT; gidx += 1024) {
        float m = sa[gidx * 8];
        #pragma unroll
        for (int k = 1; k < 8; k++) m = fmaxf(m, sa[gidx * 8 + k]);
        int b = gidx / NPT, ss = gidx % NPT;
        g_feat[b * 160 + c * 10 + ss] = m;
    }
}

__global__ void __launch_bounds__(128) fc1_kernel(
    const float* __restrict__ w, const float* __restrict__ bias,
    const float* __restrict__ g, const float* __restrict__ be) {
    const int o = blockIdx.x, b = threadIdx.x;
    const float* wr = &w[o * 160];
    const float* f  = &g_feat[b * 160];
    float acc = 0.0f;
    #pragma unroll
    for (int i = 0; i < 160; i++) acc += wr[i] * f[i];
    const float h = acc + bias[o];

    double s = h, s2 = (double)h * h;
    __shared__ double red[8];
    block_red2<4>(s, s2, red);
    __shared__ float s_sc, s_sh;
    if (b == 0) {
        double mean = s / BATCH;
        double var  = s2 / BATCH - mean * mean;
        float inv = rsqrtf((float)var + 1e-5f) * g[o];
        s_sc = inv; s_sh = be[o] - (float)mean * inv;
    }
    __syncthreads();
    g_h[b * 128 + o] = fmaxf(h * s_sc + s_sh, 0.0f);
}

__global__ void fc2_kernel(const float* __restrict__ w, const float* __restrict__ bias,
                           float* __restrict__ out) {
    const int b = blockIdx.x, o = threadIdx.x;
    if (o < 25) {
        const float* h  = &g_h[b * 128];
        const float* wr = &w[o * 128];
        float acc = 0.0f;
        #pragma unroll
        for (int i = 0; i < 128; i++) acc += h[i] * wr[i];
        out[b * 25 + o] = acc + bias[o];
    }
}

// ---------------------------------------------------------------------------
// Launch
// ---------------------------------------------------------------------------
extern "C" void kernel_launch(void* const* d_in, const int* in_sizes, int n_in,
                              void* d_out, int out_size) {
    (void)in_sizes; (void)n_in; (void)out_size;
    const float* pc    = (const float*)d_in[0];
    const float* w1    = (const float*)d_in[1];
    const float* b1    = (const float*)d_in[2];
    const float* g1    = (const float*)d_in[3];
    const float* be1   = (const float*)d_in[4];
    const float* w2    = (const float*)d_in[5];
    const float* b2    = (const float*)d_in[6];
    const float* g2    = (const float*)d_in[7];
    const float* be2   = (const float*)d_in[8];
    const float* w3    = (const float*)d_in[9];
    const float* b3    = (const float*)d_in[10];
    const float* g3    = (const float*)d_in[11];
    const float* be3   = (const float*)d_in[12];
    const float* fc1w  = (const float*)d_in[13];
    const float* fc1b  = (const float*)d_in[14];
    const float* bn1g  = (const float*)d_in[15];
    const float* bn1b  = (const float*)d_in[16];
    const float* fc2w  = (const float*)d_in[17];
    const float* fc2b  = (const float*)d_in[18];
    float* out = (float*)d_out;

    cudaFuncSetAttribute(fps_bq_kernel, cudaFuncAttributeMaxDynamicSharedMemorySize,
                         DSMEM);
    fps_bq_kernel<<<BATCH, FPS_T, DSMEM>>>(pc);
    layer1_kernel<<<8, 1024>>>(w1, b1, g1, be1);
    layer2_kernel<<<8, 1024>>>(w2, b2, g2, be2);
    layer3_kernel<<<16, 1024>>>(w3, b3, g3, be3);
    fc1_kernel<<<128, 128>>>(fc1w, fc1b, bn1g, bn1b);
    fc2_kernel<<<128, 32>>>(fc2w, fc2b, out);
}